// round 2
// baseline (speedup 1.0000x reference)
#include <cuda_runtime.h>
#include <cuda_bf16.h>
#include <math.h>
#include <float.h>

#define BATCH 96
#define NQ 35
#define LP 180
#define HID 768
#define DIM 128

#define NQ_PAD 40
#define LTILE 96
#define P_STRIDE 132   // 132 mod 32 = 4 -> conflict-free float4 LDS across lanes

// ---------------- scratch (no allocation allowed) ----------------
__device__ float g_q[BATCH * NQ * DIM];
__device__ float g_pos[BATCH * LP * DIM];
__device__ float g_neg[BATCH * LP * DIM];
__device__ float g_pmask[BATCH * LP];
__device__ float g_nmask[BATCH * LP];
__device__ int   g_mask_mode;

// ---------------- mask dtype detection ----------------
// Scans the first 17280 bytes (safe under every candidate layout) of the
// pos_mask buffer. With ~85% true density the word signatures are unambiguous:
//   bf16   -> word 0x3F803F80 appears
//   float32-> word 0x3F800000 appears (and 0x3F803F80 never does)
//   uint8  -> words > 1 (packed 0x01 bytes), no float signatures
//   int32  -> all words are 0 or 1
__global__ void detect_mode_kernel(const unsigned int* __restrict__ m) {
    __shared__ int s_bf16, s_f32, s_gt1;
    if (threadIdx.x == 0) { s_bf16 = 0; s_f32 = 0; s_gt1 = 0; }
    __syncthreads();
    int lbf = 0, lf = 0, lg = 0;
    for (int i = threadIdx.x; i < (BATCH * LP) / 4; i += blockDim.x) {
        unsigned int w = m[i];
        if (w == 0x3F803F80u) lbf = 1;
        else if (w == 0x3F800000u) lf = 1;
        else if (w > 1u) lg = 1;
    }
    if (lbf) s_bf16 = 1;
    if (lf)  s_f32 = 1;
    if (lg)  s_gt1 = 1;
    __syncthreads();
    if (threadIdx.x == 0) {
        int mode;
        if (s_bf16)      mode = 3;   // bf16
        else if (s_f32)  mode = 2;   // float32
        else if (s_gt1)  mode = 0;   // uint8
        else             mode = 1;   // int32
        g_mask_mode = mode;
    }
}

__global__ void expand_mask_kernel(const void* __restrict__ pm, const void* __restrict__ nm) {
    int idx = blockIdx.x * blockDim.x + threadIdx.x;
    if (idx >= BATCH * LP) return;
    int mode = g_mask_mode;
    float pv, nv;
    if (mode == 0) {
        pv = ((const unsigned char*)pm)[idx] ? 1.f : 0.f;
        nv = ((const unsigned char*)nm)[idx] ? 1.f : 0.f;
    } else if (mode == 1) {
        pv = ((const int*)pm)[idx] ? 1.f : 0.f;
        nv = ((const int*)nm)[idx] ? 1.f : 0.f;
    } else if (mode == 2) {
        pv = (((const float*)pm)[idx] != 0.f) ? 1.f : 0.f;
        nv = (((const float*)nm)[idx] != 0.f) ? 1.f : 0.f;
    } else {
        pv = (__bfloat162float(((const __nv_bfloat16*)pm)[idx]) != 0.f) ? 1.f : 0.f;
        nv = (__bfloat162float(((const __nv_bfloat16*)nm)[idx]) != 0.f) ? 1.f : 0.f;
    }
    g_pmask[idx] = pv;
    g_nmask[idx] = nv;
}

// ---------------- projection GEMM: out[M,128] = A[M,768] @ W[768,128] + b ----------------
// Block tile 64x128, K-chunk 16, 256 threads, per-thread 8x4 micro-tile.
__global__ __launch_bounds__(256) void proj_kernel(
    const float* __restrict__ A, const float* __restrict__ W,
    const float* __restrict__ bias, float* __restrict__ out, int M)
{
    __shared__ float As[64 * 16];
    __shared__ float Bs[16 * 128];
    int tid = threadIdx.x;
    int row0 = blockIdx.x * 64;
    int ty = tid >> 5;     // 0..7  -> 8 rows each
    int tx = tid & 31;     // 0..31 -> 4 cols each

    float acc[8][4];
    #pragma unroll
    for (int i = 0; i < 8; i++)
        #pragma unroll
        for (int c = 0; c < 4; c++) acc[i][c] = 0.f;

    int alr = tid >> 2;          // 0..63
    int alc = (tid & 3) * 4;     // 0,4,8,12
    const float* Arow = A + (size_t)(row0 + alr) * HID;
    bool arow_ok = (row0 + alr) < M;

    for (int kt = 0; kt < HID; kt += 16) {
        float4 av = make_float4(0.f, 0.f, 0.f, 0.f);
        if (arow_ok) av = *(const float4*)(Arow + kt + alc);
        *(float4*)&As[alr * 16 + alc] = av;
        #pragma unroll
        for (int s = 0; s < 2; s++) {
            int idx = tid + 256 * s;
            int br = idx >> 5;
            int bc = (idx & 31) * 4;
            *(float4*)&Bs[br * 128 + bc] =
                *(const float4*)(W + (size_t)(kt + br) * DIM + bc);
        }
        __syncthreads();
        #pragma unroll
        for (int kk = 0; kk < 16; kk++) {
            float4 bv = *(float4*)&Bs[kk * 128 + tx * 4];
            #pragma unroll
            for (int i = 0; i < 8; i++) {
                float a = As[(ty * 8 + i) * 16 + kk];
                acc[i][0] += a * bv.x;
                acc[i][1] += a * bv.y;
                acc[i][2] += a * bv.z;
                acc[i][3] += a * bv.w;
            }
        }
        __syncthreads();
    }

    float4 bb = *(const float4*)(bias + tx * 4);
    #pragma unroll
    for (int i = 0; i < 8; i++) {
        int r = row0 + ty * 8 + i;
        if (r < M) {
            float4 o;
            o.x = acc[i][0] + bb.x;
            o.y = acc[i][1] + bb.y;
            o.z = acc[i][2] + bb.z;
            o.w = acc[i][3] + bb.w;
            *(float4*)(out + (size_t)r * DIM + tx * 4) = o;
        }
    }
}

// ---------------- normalization over the SEQUENCE axis (axis=1, keepdims) ----------------
__global__ void norm_kernel(float* __restrict__ x, int L) {
    int idx = blockIdx.x * blockDim.x + threadIdx.x;
    if (idx >= BATCH * DIM) return;
    int b = idx >> 7;
    int d = idx & 127;
    float* base = x + (size_t)b * L * DIM + d;
    float s = 0.f;
    for (int l = 0; l < L; l++) { float v = base[(size_t)l * DIM]; s += v * v; }
    float inv = 1.f / fmaxf(sqrtf(s), 1e-12f);
    for (int l = 0; l < L; l++) base[(size_t)l * DIM] *= inv;
}

// ---------------- MaxSim late interaction ----------------
// One block per (bp = blockIdx.x, bq = blockIdx.y). 256 threads = 8 warps.
// warp ny owns q rows [ny*5, ny*5+5); lane lx owns p rows {lx, lx+32, lx+64} of each 96-l tile.
__global__ __launch_bounds__(256) void maxsim_kernel(
    const float* __restrict__ Q, const float* __restrict__ P,
    const float* __restrict__ Mf, float* __restrict__ out, int col_off)
{
    extern __shared__ float sm[];
    float* q_s = sm;                         // NQ_PAD*DIM   = 5120 floats
    float* p_s = sm + NQ_PAD * DIM;          // LTILE*P_STRIDE = 12672 floats
    float* m_s = p_s + LTILE * P_STRIDE;     // LTILE floats
    __shared__ float warp_sums[8];

    int bp = blockIdx.x, bq = blockIdx.y;
    int tid = threadIdx.x;
    int ny = tid >> 5;
    int lx = tid & 31;

    // load q tile (pad rows 35..39 with zeros)
    for (int i = tid; i < NQ_PAD * 32; i += 256) {
        int r = i >> 5, c = (i & 31) * 4;
        float4 v = make_float4(0.f, 0.f, 0.f, 0.f);
        if (r < NQ) v = *(const float4*)(Q + ((size_t)(bq * NQ + r)) * DIM + c);
        *(float4*)&q_s[r * DIM + c] = v;
    }

    float nmax[5];
    #pragma unroll
    for (int i = 0; i < 5; i++) nmax[i] = -FLT_MAX;

    for (int t = 0; t < 2; t++) {
        __syncthreads();
        for (int i = tid; i < LTILE * 32; i += 256) {
            int r = i >> 5, c = (i & 31) * 4;
            int l = t * LTILE + r;
            float4 v = make_float4(0.f, 0.f, 0.f, 0.f);
            if (l < LP) v = *(const float4*)(P + ((size_t)(bp * LP + l)) * DIM + c);
            *(float4*)&p_s[r * P_STRIDE + c] = v;
        }
        if (tid < LTILE) {
            int l = t * LTILE + tid;
            m_s[tid] = (l < LP) ? Mf[bp * LP + l] : 0.f;
        }
        __syncthreads();

        float acc[5][3];
        #pragma unroll
        for (int i = 0; i < 5; i++)
            #pragma unroll
            for (int j = 0; j < 3; j++) acc[i][j] = 0.f;

        #pragma unroll 4
        for (int k = 0; k < DIM; k += 4) {
            float4 qv[5], pv[3];
            #pragma unroll
            for (int i = 0; i < 5; i++)
                qv[i] = *(const float4*)&q_s[(ny * 5 + i) * DIM + k];
            #pragma unroll
            for (int j = 0; j < 3; j++)
                pv[j] = *(const float4*)&p_s[(lx + 32 * j) * P_STRIDE + k];
            #pragma unroll
            for (int i = 0; i < 5; i++)
                #pragma unroll
                for (int j = 0; j < 3; j++) {
                    acc[i][j] += qv[i].x * pv[j].x;
                    acc[i][j] += qv[i].y * pv[j].y;
                    acc[i][j] += qv[i].z * pv[j].z;
                    acc[i][j] += qv[i].w * pv[j].w;
                }
        }

        #pragma unroll
        for (int j = 0; j < 3; j++) {
            if (m_s[lx + 32 * j] != 0.f) {
                #pragma unroll
                for (int i = 0; i < 5; i++)
                    nmax[i] = fmaxf(nmax[i], acc[i][j]);
            }
        }
    }

    // max over l: reduce across the 32 lanes of each warp
    #pragma unroll
    for (int i = 0; i < 5; i++) {
        #pragma unroll
        for (int o = 16; o > 0; o >>= 1)
            nmax[i] = fmaxf(nmax[i], __shfl_xor_sync(0xffffffffu, nmax[i], o));
    }
    if (lx == 0) {
        float s = 0.f;
        #pragma unroll
        for (int i = 0; i < 5; i++)
            if (ny * 5 + i < NQ) s += nmax[i];
        warp_sums[ny] = s;
    }
    __syncthreads();
    if (tid == 0) {
        float s = 0.f;
        #pragma unroll
        for (int w = 0; w < 8; w++) s += warp_sums[w];
        out[(size_t)bq * (2 * BATCH) + col_off + bp] = s;
    }
}

// ---------------- launch ----------------
extern "C" void kernel_launch(void* const* d_in, const int* in_sizes, int n_in,
                              void* d_out, int out_size)
{
    const float* qh   = (const float*)d_in[0];
    const float* ph   = (const float*)d_in[1];
    const float* nh   = (const float*)d_in[2];
    const float* W    = (const float*)d_in[3];
    const float* bias = (const float*)d_in[4];
    const void*  pm   = d_in[5];
    const void*  nm   = d_in[6];
    float* out = (float*)d_out;

    float *dq, *dpos, *dneg, *dpm, *dnm;
    cudaGetSymbolAddress((void**)&dq,   g_q);
    cudaGetSymbolAddress((void**)&dpos, g_pos);
    cudaGetSymbolAddress((void**)&dneg, g_neg);
    cudaGetSymbolAddress((void**)&dpm,  g_pmask);
    cudaGetSymbolAddress((void**)&dnm,  g_nmask);

    detect_mode_kernel<<<1, 256>>>((const unsigned int*)pm);
    expand_mask_kernel<<<(BATCH * LP + 255) / 256, 256>>>(pm, nm);

    proj_kernel<<<(BATCH * NQ + 63) / 64, 256>>>(qh, W, bias, dq, BATCH * NQ);
    proj_kernel<<<(BATCH * LP + 63) / 64, 256>>>(ph, W, bias, dpos, BATCH * LP);
    proj_kernel<<<(BATCH * LP + 63) / 64, 256>>>(nh, W, bias, dneg, BATCH * LP);

    norm_kernel<<<(BATCH * DIM + 255) / 256, 256>>>(dq, NQ);
    norm_kernel<<<(BATCH * DIM + 255) / 256, 256>>>(dpos, LP);
    norm_kernel<<<(BATCH * DIM + 255) / 256, 256>>>(dneg, LP);

    int smem = (NQ_PAD * DIM + LTILE * P_STRIDE + LTILE) * (int)sizeof(float);
    cudaFuncSetAttribute(maxsim_kernel, cudaFuncAttributeMaxDynamicSharedMemorySize, smem);
    dim3 grid(BATCH, BATCH);
    maxsim_kernel<<<grid, 256, smem>>>(dq, dpos, dpm, out, 0);
    maxsim_kernel<<<grid, 256, smem>>>(dq, dneg, dnm, out, BATCH);
}

// round 3
// speedup vs baseline: 1.0225x; 1.0225x over previous
#include <cuda_runtime.h>
#include <cuda_bf16.h>
#include <math.h>
#include <float.h>

#define BATCH 96
#define NQ 35
#define LP 180
#define HID 768
#define DIM 128

#define LTILE 96
#define P_STRIDE 132   // 132 mod 32 = 4 -> conflict-free float4 LDS phases
#define TQ 9           // q rows per thread (ty)
#define TP 6           // p rows per thread (tx), rows tx + 16*j
#define QROWS 144      // 4 bq * 36 (35 real + 1 zero pad each)

// packed fp32x2 FMA: d.lo += a.lo*b.lo ; d.hi += a.hi*b.hi  (full 2xFP32 rate)
#define FMA2(d, a, b) asm("fma.rn.f32x2 %0, %1, %2, %0;" : "+l"(d) : "l"(a), "l"(b))

__device__ __forceinline__ float f2sum(unsigned long long v) {
    float lo = __uint_as_float((unsigned)(v & 0xffffffffull));
    float hi = __uint_as_float((unsigned)(v >> 32));
    return lo + hi;
}

// ---------------- scratch (no allocation allowed) ----------------
__device__ float g_q[BATCH * NQ * DIM];
__device__ float g_pos[BATCH * LP * DIM];
__device__ float g_neg[BATCH * LP * DIM];
__device__ float g_pmask[BATCH * LP];
__device__ float g_nmask[BATCH * LP];
__device__ int   g_mask_mode;

// ---------------- mask dtype detection ----------------
__global__ void detect_mode_kernel(const unsigned int* __restrict__ m) {
    __shared__ int s_bf16, s_f32, s_gt1;
    if (threadIdx.x == 0) { s_bf16 = 0; s_f32 = 0; s_gt1 = 0; }
    __syncthreads();
    int lbf = 0, lf = 0, lg = 0;
    for (int i = threadIdx.x; i < (BATCH * LP) / 4; i += blockDim.x) {
        unsigned int w = m[i];
        if (w == 0x3F803F80u) lbf = 1;
        else if (w == 0x3F800000u) lf = 1;
        else if (w > 1u) lg = 1;
    }
    if (lbf) s_bf16 = 1;
    if (lf)  s_f32 = 1;
    if (lg)  s_gt1 = 1;
    __syncthreads();
    if (threadIdx.x == 0) {
        int mode;
        if (s_bf16)      mode = 3;   // bf16
        else if (s_f32)  mode = 2;   // float32
        else if (s_gt1)  mode = 0;   // uint8
        else             mode = 1;   // int32
        g_mask_mode = mode;
    }
}

__global__ void expand_mask_kernel(const void* __restrict__ pm, const void* __restrict__ nm) {
    int idx = blockIdx.x * blockDim.x + threadIdx.x;
    if (idx >= BATCH * LP) return;
    int mode = g_mask_mode;
    float pv, nv;
    if (mode == 0) {
        pv = ((const unsigned char*)pm)[idx] ? 1.f : 0.f;
        nv = ((const unsigned char*)nm)[idx] ? 1.f : 0.f;
    } else if (mode == 1) {
        pv = ((const int*)pm)[idx] ? 1.f : 0.f;
        nv = ((const int*)nm)[idx] ? 1.f : 0.f;
    } else if (mode == 2) {
        pv = (((const float*)pm)[idx] != 0.f) ? 1.f : 0.f;
        nv = (((const float*)nm)[idx] != 0.f) ? 1.f : 0.f;
    } else {
        pv = (__bfloat162float(((const __nv_bfloat16*)pm)[idx]) != 0.f) ? 1.f : 0.f;
        nv = (__bfloat162float(((const __nv_bfloat16*)nm)[idx]) != 0.f) ? 1.f : 0.f;
    }
    g_pmask[idx] = pv;
    g_nmask[idx] = nv;
}

// ---------------- projection GEMM (f32x2 packed): out[M,128] = A[M,768] @ W + b ----------------
__global__ __launch_bounds__(256) void proj_kernel(
    const float* __restrict__ A, const float* __restrict__ W,
    const float* __restrict__ bias, float* __restrict__ out, int M)
{
    __shared__ float As[64 * 16];
    __shared__ float Bs[16 * 128];
    int tid = threadIdx.x;
    int row0 = blockIdx.x * 64;
    int ty = tid >> 5;     // 0..7  -> 8 rows each
    int tx = tid & 31;     // 0..31 -> 4 cols each

    unsigned long long acc2[8][2];
    #pragma unroll
    for (int i = 0; i < 8; i++) { acc2[i][0] = 0ull; acc2[i][1] = 0ull; }

    int alr = tid >> 2;
    int alc = (tid & 3) * 4;
    const float* Arow = A + (size_t)(row0 + alr) * HID;
    bool arow_ok = (row0 + alr) < M;

    for (int kt = 0; kt < HID; kt += 16) {
        float4 av = make_float4(0.f, 0.f, 0.f, 0.f);
        if (arow_ok) av = *(const float4*)(Arow + kt + alc);
        *(float4*)&As[alr * 16 + alc] = av;
        #pragma unroll
        for (int s = 0; s < 2; s++) {
            int idx = tid + 256 * s;
            int br = idx >> 5;
            int bc = (idx & 31) * 4;
            *(float4*)&Bs[br * 128 + bc] =
                *(const float4*)(W + (size_t)(kt + br) * DIM + bc);
        }
        __syncthreads();
        #pragma unroll
        for (int kk = 0; kk < 16; kk++) {
            ulonglong2 bv = *(ulonglong2*)&Bs[kk * 128 + tx * 4];
            #pragma unroll
            for (int i = 0; i < 8; i++) {
                float a = As[(ty * 8 + i) * 16 + kk];
                float2 aa = make_float2(a, a);
                unsigned long long a2 = *(unsigned long long*)&aa;
                FMA2(acc2[i][0], a2, bv.x);
                FMA2(acc2[i][1], a2, bv.y);
            }
        }
        __syncthreads();
    }

    float4 bb = *(const float4*)(bias + tx * 4);
    #pragma unroll
    for (int i = 0; i < 8; i++) {
        int r = row0 + ty * 8 + i;
        if (r < M) {
            float2 p0 = *(float2*)&acc2[i][0];
            float2 p1 = *(float2*)&acc2[i][1];
            float4 o;
            o.x = p0.x + bb.x;
            o.y = p0.y + bb.y;
            o.z = p1.x + bb.z;
            o.w = p1.y + bb.w;
            *(float4*)(out + (size_t)r * DIM + tx * 4) = o;
        }
    }
}

// ---------------- normalization over the SEQUENCE axis (axis=1, keepdims) ----------------
__global__ void norm_kernel(float* __restrict__ x, int L) {
    int idx = blockIdx.x * blockDim.x + threadIdx.x;
    if (idx >= BATCH * DIM) return;
    int b = idx >> 7;
    int d = idx & 127;
    float* base = x + (size_t)b * L * DIM + d;
    float s = 0.f;
    for (int l = 0; l < L; l++) { float v = base[(size_t)l * DIM]; s += v * v; }
    float inv = 1.f / fmaxf(sqrtf(s), 1e-12f);
    for (int l = 0; l < L; l++) base[(size_t)l * DIM] *= inv;
}

// ---------------- MaxSim late interaction (f32x2 packed) ----------------
// grid = (bp=96, bqg=24, side=2). Block: 256 threads = 16(tx: p dim) x 16(ty: q dim).
// q tile: 4 batches x 36 rows (row 35 of each = zero pad) = 144 rows.
// p tile: 96 rows x 2 tiles over Lp=180 (rows >=180 zero, mask 0).
// Per-thread micro-tile: TQ=9 q rows x TP=6 p rows, packed f32x2 accumulators.
__global__ __launch_bounds__(256, 1) void maxsim_kernel(
    const float* __restrict__ Q,
    const float* __restrict__ Ppos, const float* __restrict__ Pneg,
    const float* __restrict__ Mpos, const float* __restrict__ Mneg,
    float* __restrict__ out)
{
    extern __shared__ float sm[];
    float* q_s = sm;                          // QROWS*DIM = 18432 floats
    float* p_s = sm + QROWS * DIM;            // LTILE*P_STRIDE = 12672 floats
    float* m_s = p_s + LTILE * P_STRIDE;      // LTILE floats
    __shared__ float s_part[16];

    int bp = blockIdx.x, bqg = blockIdx.y, z = blockIdx.z;
    const float* P  = z ? Pneg : Ppos;
    const float* Mf = z ? Mneg : Mpos;

    int tid = threadIdx.x;
    int tx = tid & 15;
    int ty = tid >> 4;

    // load q tile (4 bq, 36 rows each, row 35 zero)
    for (int i = tid; i < QROWS * 32; i += 256) {
        int r = i >> 5, c = (i & 31) * 4;
        int rb = r / 36, rr = r - rb * 36;
        float4 v = make_float4(0.f, 0.f, 0.f, 0.f);
        if (rr < NQ)
            v = *(const float4*)(Q + ((size_t)((bqg * 4 + rb) * NQ + rr)) * DIM + c);
        *(float4*)&q_s[r * DIM + c] = v;
    }

    float nmax[TQ];
    #pragma unroll
    for (int i = 0; i < TQ; i++) nmax[i] = -FLT_MAX;

    for (int t = 0; t < 2; t++) {
        __syncthreads();
        for (int i = tid; i < LTILE * 32; i += 256) {
            int r = i >> 5, c = (i & 31) * 4;
            int l = t * LTILE + r;
            float4 v = make_float4(0.f, 0.f, 0.f, 0.f);
            if (l < LP) v = *(const float4*)(P + ((size_t)(bp * LP + l)) * DIM + c);
            *(float4*)&p_s[r * P_STRIDE + c] = v;
        }
        if (tid < LTILE) {
            int l = t * LTILE + tid;
            m_s[tid] = (l < LP) ? Mf[bp * LP + l] : 0.f;
        }
        __syncthreads();

        unsigned long long acc[TQ][TP];
        #pragma unroll
        for (int i = 0; i < TQ; i++)
            #pragma unroll
            for (int j = 0; j < TP; j++) acc[i][j] = 0ull;

        #pragma unroll 2
        for (int k = 0; k < DIM; k += 4) {
            ulonglong2 pv[TP];
            #pragma unroll
            for (int j = 0; j < TP; j++)
                pv[j] = *(const ulonglong2*)&p_s[(tx + 16 * j) * P_STRIDE + k];
            #pragma unroll
            for (int i = 0; i < TQ; i++) {
                ulonglong2 qv = *(const ulonglong2*)&q_s[(ty * TQ + i) * DIM + k];
                #pragma unroll
                for (int j = 0; j < TP; j++) {
                    FMA2(acc[i][j], qv.x, pv[j].x);
                    FMA2(acc[i][j], qv.y, pv[j].y);
                }
            }
        }

        #pragma unroll
        for (int j = 0; j < TP; j++) {
            if (m_s[tx + 16 * j] != 0.f) {
                #pragma unroll
                for (int i = 0; i < TQ; i++)
                    nmax[i] = fmaxf(nmax[i], f2sum(acc[i][j]));
            }
        }
    }

    // max over the 16 tx lanes (xor offsets 1..8 stay within 16-lane halves)
    #pragma unroll
    for (int i = 0; i < TQ; i++) {
        #pragma unroll
        for (int o = 8; o > 0; o >>= 1)
            nmax[i] = fmaxf(nmax[i], __shfl_xor_sync(0xffffffffu, nmax[i], o));
    }
    if (tx == 0) {
        float s = 0.f;
        #pragma unroll
        for (int i = 0; i < TQ; i++) {
            int r = ty * TQ + i;
            if (r % 36 != 35) s += nmax[i];   // skip zero-pad rows
        }
        s_part[ty] = s;
    }
    __syncthreads();
    if (tid < 4) {  // tid = local bq index; its rows are ty in [4*tid, 4*tid+4)
        float s = s_part[tid * 4] + s_part[tid * 4 + 1]
                + s_part[tid * 4 + 2] + s_part[tid * 4 + 3];
        out[(size_t)(bqg * 4 + tid) * (2 * BATCH) + z * BATCH + bp] = s;
    }
}

// ---------------- launch ----------------
extern "C" void kernel_launch(void* const* d_in, const int* in_sizes, int n_in,
                              void* d_out, int out_size)
{
    const float* qh   = (const float*)d_in[0];
    const float* ph   = (const float*)d_in[1];
    const float* nh   = (const float*)d_in[2];
    const float* W    = (const float*)d_in[3];
    const float* bias = (const float*)d_in[4];
    const void*  pm   = d_in[5];
    const void*  nm   = d_in[6];
    float* out = (float*)d_out;

    float *dq, *dpos, *dneg, *dpm, *dnm;
    cudaGetSymbolAddress((void**)&dq,   g_q);
    cudaGetSymbolAddress((void**)&dpos, g_pos);
    cudaGetSymbolAddress((void**)&dneg, g_neg);
    cudaGetSymbolAddress((void**)&dpm,  g_pmask);
    cudaGetSymbolAddress((void**)&dnm,  g_nmask);

    detect_mode_kernel<<<1, 256>>>((const unsigned int*)pm);
    expand_mask_kernel<<<(BATCH * LP + 255) / 256, 256>>>(pm, nm);

    proj_kernel<<<(BATCH * NQ + 63) / 64, 256>>>(qh, W, bias, dq, BATCH * NQ);
    proj_kernel<<<(BATCH * LP + 63) / 64, 256>>>(ph, W, bias, dpos, BATCH * LP);
    proj_kernel<<<(BATCH * LP + 63) / 64, 256>>>(nh, W, bias, dneg, BATCH * LP);

    norm_kernel<<<(BATCH * DIM + 255) / 256, 256>>>(dq, NQ);
    norm_kernel<<<(BATCH * DIM + 255) / 256, 256>>>(dpos, LP);
    norm_kernel<<<(BATCH * DIM + 255) / 256, 256>>>(dneg, LP);

    int smem = (QROWS * DIM + LTILE * P_STRIDE + LTILE) * (int)sizeof(float);
    cudaFuncSetAttribute(maxsim_kernel, cudaFuncAttributeMaxDynamicSharedMemorySize, smem);
    dim3 grid(BATCH, BATCH / 4, 2);
    maxsim_kernel<<<grid, 256, smem>>>(dq, dpos, dneg, dpm, dnm, out);
}

// round 7
// speedup vs baseline: 1.9222x; 1.8799x over previous
#include <cuda_runtime.h>
#include <cuda_bf16.h>
#include <math.h>
#include <float.h>
#include <stdint.h>

#define BATCH 96
#define NQ 35
#define LP 180
#define HID 768
#define DIM 128

// ===================== scratch =====================
__device__ float g_q[BATCH * NQ * DIM];
__device__ float g_pos[BATCH * LP * DIM];
__device__ float g_neg[BATCH * LP * DIM];
__device__ float g_pmask[BATCH * LP];
__device__ float g_nmask[BATCH * LP];
__device__ int   g_mask_mode;

// ===================== mask dtype detection =====================
__global__ void detect_mode_kernel(const unsigned int* __restrict__ m) {
    __shared__ int s_bf16, s_f32, s_gt1;
    if (threadIdx.x == 0) { s_bf16 = 0; s_f32 = 0; s_gt1 = 0; }
    __syncthreads();
    int lbf = 0, lf = 0, lg = 0;
    for (int i = threadIdx.x; i < (BATCH * LP) / 4; i += blockDim.x) {
        unsigned int w = m[i];
        if (w == 0x3F803F80u) lbf = 1;
        else if (w == 0x3F800000u) lf = 1;
        else if (w > 1u) lg = 1;
    }
    if (lbf) s_bf16 = 1;
    if (lf)  s_f32 = 1;
    if (lg)  s_gt1 = 1;
    __syncthreads();
    if (threadIdx.x == 0) {
        int mode;
        if (s_bf16)      mode = 3;
        else if (s_f32)  mode = 2;
        else if (s_gt1)  mode = 0;
        else             mode = 1;
        g_mask_mode = mode;
    }
}

__global__ void expand_mask_kernel(const void* __restrict__ pm, const void* __restrict__ nm) {
    int idx = blockIdx.x * blockDim.x + threadIdx.x;
    if (idx >= BATCH * LP) return;
    int mode = g_mask_mode;
    float pv, nv;
    if (mode == 0) {
        pv = ((const unsigned char*)pm)[idx] ? 1.f : 0.f;
        nv = ((const unsigned char*)nm)[idx] ? 1.f : 0.f;
    } else if (mode == 1) {
        pv = ((const int*)pm)[idx] ? 1.f : 0.f;
        nv = ((const int*)nm)[idx] ? 1.f : 0.f;
    } else if (mode == 2) {
        pv = (((const float*)pm)[idx] != 0.f) ? 1.f : 0.f;
        nv = (((const float*)nm)[idx] != 0.f) ? 1.f : 0.f;
    } else {
        pv = (__bfloat162float(((const __nv_bfloat16*)pm)[idx]) != 0.f) ? 1.f : 0.f;
        nv = (__bfloat162float(((const __nv_bfloat16*)nm)[idx]) != 0.f) ? 1.f : 0.f;
    }
    g_pmask[idx] = pv;
    g_nmask[idx] = nv;
}

// ===================== projection GEMM (FFMA, round-2 form) =====================
__global__ __launch_bounds__(256) void proj_kernel(
    const float* __restrict__ A, const float* __restrict__ W,
    const float* __restrict__ bias, float* __restrict__ out, int M)
{
    __shared__ float As[64 * 16];
    __shared__ float Bs[16 * 128];
    int tid = threadIdx.x;
    int row0 = blockIdx.x * 64;
    int ty = tid >> 5;
    int tx = tid & 31;

    float acc[8][4];
    #pragma unroll
    for (int i = 0; i < 8; i++)
        #pragma unroll
        for (int c = 0; c < 4; c++) acc[i][c] = 0.f;

    int alr = tid >> 2;
    int alc = (tid & 3) * 4;
    const float* Arow = A + (size_t)(row0 + alr) * HID;
    bool arow_ok = (row0 + alr) < M;

    for (int kt = 0; kt < HID; kt += 16) {
        float4 av = make_float4(0.f, 0.f, 0.f, 0.f);
        if (arow_ok) av = *(const float4*)(Arow + kt + alc);
        *(float4*)&As[alr * 16 + alc] = av;
        #pragma unroll
        for (int s = 0; s < 2; s++) {
            int idx = tid + 256 * s;
            int br = idx >> 5;
            int bc = (idx & 31) * 4;
            *(float4*)&Bs[br * 128 + bc] =
                *(const float4*)(W + (size_t)(kt + br) * DIM + bc);
        }
        __syncthreads();
        #pragma unroll
        for (int kk = 0; kk < 16; kk++) {
            float4 bv = *(float4*)&Bs[kk * 128 + tx * 4];
            #pragma unroll
            for (int i = 0; i < 8; i++) {
                float a = As[(ty * 8 + i) * 16 + kk];
                acc[i][0] += a * bv.x;
                acc[i][1] += a * bv.y;
                acc[i][2] += a * bv.z;
                acc[i][3] += a * bv.w;
            }
        }
        __syncthreads();
    }

    float4 bb = *(const float4*)(bias + tx * 4);
    #pragma unroll
    for (int i = 0; i < 8; i++) {
        int r = row0 + ty * 8 + i;
        if (r < M) {
            float4 o;
            o.x = acc[i][0] + bb.x;
            o.y = acc[i][1] + bb.y;
            o.z = acc[i][2] + bb.z;
            o.w = acc[i][3] + bb.w;
            *(float4*)(out + (size_t)r * DIM + tx * 4) = o;
        }
    }
}

// ===================== sequence-axis normalization =====================
__global__ void norm_kernel(float* __restrict__ x, int L) {
    int idx = blockIdx.x * blockDim.x + threadIdx.x;
    if (idx >= BATCH * DIM) return;
    int b = idx >> 7;
    int d = idx & 127;
    float* base = x + (size_t)b * L * DIM + d;
    float s = 0.f;
    for (int l = 0; l < L; l++) { float v = base[(size_t)l * DIM]; s += v * v; }
    float inv = 1.f / fmaxf(sqrtf(s), 1e-12f);
    for (int l = 0; l < L; l++) base[(size_t)l * DIM] *= inv;
}

// ===================== mma.sync MaxSim =====================
// Block = (bp, group of 3 bq, side). M = 3*35 = 105 padded to 128 rows;
// Lp = 180 via two overlapping N=96 halves (l0 = 0, 84).
// smem: qh/ql [128 x 128 bf16] and ph/pl [96 x 128 bf16], rows of 16 chunks
// of 16B, swizzled chunk ^= (row & 7) for conflict-free ldmatrix.
// sim = qh*ph + qh*pl + ql*ph accumulated in fp32 C-frags across all 3 terms
// and 8 k16 steps. Mask as additive bias in epilogue; max-over-l via smem
// atomicMax on monotone-encoded floats.

#define QH_OFF 0
#define QL_OFF 32768
#define PH_OFF 65536
#define PL_OFF 90112
#define MS_SMEM (90112 + 24576)     // 112 KB dynamic

__device__ __forceinline__ uint32_t smem_u32(const void* p) {
    uint32_t a;
    asm("{ .reg .u64 t; cvta.to.shared.u64 t, %1; cvt.u32.u64 %0, t; }" : "=r"(a) : "l"(p));
    return a;
}

#define LDSM_X4(r0, r1, r2, r3, addr) \
    asm volatile("ldmatrix.sync.aligned.m8n8.x4.shared.b16 {%0,%1,%2,%3}, [%4];" \
        : "=r"(r0), "=r"(r1), "=r"(r2), "=r"(r3) : "r"(addr))

#define MMA_BF16(c, a, b) \
    asm volatile("mma.sync.aligned.m16n8k16.row.col.f32.bf16.bf16.f32 " \
        "{%0,%1,%2,%3}, {%4,%5,%6,%7}, {%8,%9}, {%0,%1,%2,%3};" \
        : "+f"((c)[0]), "+f"((c)[1]), "+f"((c)[2]), "+f"((c)[3]) \
        : "r"((a)[0]), "r"((a)[1]), "r"((a)[2]), "r"((a)[3]), \
          "r"((b)[0]), "r"((b)[1]))

__device__ __forceinline__ uint32_t pack_bf16(float f0, float f1) {
    uint16_t u0 = __bfloat16_as_ushort(__float2bfloat16(f0));
    uint16_t u1 = __bfloat16_as_ushort(__float2bfloat16(f1));
    return (uint32_t)u0 | ((uint32_t)u1 << 16);
}
__device__ __forceinline__ float bf16_res(float f) {   // exact in fp32
    return f - __bfloat162float(__float2bfloat16(f));
}
__device__ __forceinline__ unsigned enc_f(float x) {   // monotone float->uint
    unsigned u = __float_as_uint(x);
    return (u & 0x80000000u) ? ~u : (u | 0x80000000u);
}
__device__ __forceinline__ float dec_f(unsigned e) {
    return (e & 0x80000000u) ? __uint_as_float(e ^ 0x80000000u)
                             : __uint_as_float(~e);
}

__global__ __launch_bounds__(256, 2) void maxsim_mma_kernel(
    const float* __restrict__ Q,
    const float* __restrict__ Ppos, const float* __restrict__ Pneg,
    const float* __restrict__ Mpos, const float* __restrict__ Mneg,
    float* __restrict__ out)
{
    extern __shared__ char sm[];
    uint32_t smb = smem_u32(sm);
    __shared__ float    bias_s[96];
    __shared__ unsigned rowmax[128];

    int bp = blockIdx.x, bqg = blockIdx.y, z = blockIdx.z;
    const float* P  = z ? Pneg : Ppos;
    const float* Mf = z ? Mneg : Mpos;
    int tid  = threadIdx.x;
    int lane = tid & 31;
    int wid  = tid >> 5;
    int mw = wid >> 1;          // 0..3  (rows 32*mw .. +31)
    int nw = wid & 1;           // 0..1  (cols 48*nw .. +47)

    if (tid < 128) rowmax[tid] = 0u;

    // ---- q -> smem (hi & lo), swizzled. 128 rows x 16 chunks.
    for (int i = tid; i < 128 * 16; i += 256) {
        int r = i >> 4, c = i & 15;
        int bq = r / 35, nq = r - bq * 35;
        bool ok = r < 105;
        float4 v0 = make_float4(0.f, 0.f, 0.f, 0.f), v1 = v0;
        if (ok) {
            const float* qrow = Q + ((size_t)((bqg * 3 + bq) * NQ + nq)) * DIM + c * 8;
            v0 = *(const float4*)qrow;
            v1 = *(const float4*)(qrow + 4);
        }
        uint32_t off = (uint32_t)r * 256u + (uint32_t)(c ^ (r & 7)) * 16u;
        uint4 hv, lv;
        hv.x = pack_bf16(v0.x, v0.y); hv.y = pack_bf16(v0.z, v0.w);
        hv.z = pack_bf16(v1.x, v1.y); hv.w = pack_bf16(v1.z, v1.w);
        lv.x = pack_bf16(bf16_res(v0.x), bf16_res(v0.y));
        lv.y = pack_bf16(bf16_res(v0.z), bf16_res(v0.w));
        lv.z = pack_bf16(bf16_res(v1.x), bf16_res(v1.y));
        lv.w = pack_bf16(bf16_res(v1.z), bf16_res(v1.w));
        *(uint4*)(sm + QH_OFF + off) = hv;
        *(uint4*)(sm + QL_OFF + off) = lv;
    }

    // precomputed ldmatrix lane address components
    int a_row  = lane & 15;            // + tile base
    int a_chnk = lane >> 4;            // 0/1 within k16
    int b_row  = ((lane & 16) >> 1) + (lane & 7);   // + 16*j + 48*nw
    int b_chnk = (lane >> 3) & 1;

    #pragma unroll
    for (int h = 0; h < 2; h++) {
        int l0 = h * 84;   // halves cover l 0..95 and 84..179 (overlap OK under max)
        __syncthreads();   // protect p buffers / bias from previous iteration readers

        // ---- p -> smem (hi & lo), swizzled. 96 rows x 16 chunks.
        for (int i = tid; i < 96 * 16; i += 256) {
            int r = i >> 4, c = i & 15;
            const float* prow = P + ((size_t)(bp * LP + l0 + r)) * DIM + c * 8;
            float4 v0 = *(const float4*)prow;
            float4 v1 = *(const float4*)(prow + 4);
            uint32_t off = (uint32_t)r * 256u + (uint32_t)(c ^ (r & 7)) * 16u;
            uint4 hv, lv;
            hv.x = pack_bf16(v0.x, v0.y); hv.y = pack_bf16(v0.z, v0.w);
            hv.z = pack_bf16(v1.x, v1.y); hv.w = pack_bf16(v1.z, v1.w);
            lv.x = pack_bf16(bf16_res(v0.x), bf16_res(v0.y));
            lv.y = pack_bf16(bf16_res(v0.z), bf16_res(v0.w));
            lv.z = pack_bf16(bf16_res(v1.x), bf16_res(v1.y));
            lv.w = pack_bf16(bf16_res(v1.z), bf16_res(v1.w));
            *(uint4*)(sm + PH_OFF + off) = hv;
            *(uint4*)(sm + PL_OFF + off) = lv;
        }
        if (tid < 96)
            bias_s[tid] = (Mf[bp * LP + l0 + tid] != 0.f) ? 0.f : -1e6f;
        __syncthreads();

        // ---- MMA mainloop: accumulate 3 terms x 8 k-steps into C
        float cfr[2][6][4];
        #pragma unroll
        for (int mi = 0; mi < 2; mi++)
            #pragma unroll
            for (int t = 0; t < 6; t++)
                #pragma unroll
                for (int u = 0; u < 4; u++) cfr[mi][t][u] = 0.f;

        #pragma unroll
        for (int k = 0; k < 8; k++) {
            uint32_t aqh[2][4], aql[2][4], bph[6][2], bpl[6][2];
            #pragma unroll
            for (int mi = 0; mi < 2; mi++) {
                int row = 32 * mw + 16 * mi + a_row;
                uint32_t off = (uint32_t)row * 256u
                             + (uint32_t)((2 * k + a_chnk) ^ (row & 7)) * 16u;
                LDSM_X4(aqh[mi][0], aqh[mi][1], aqh[mi][2], aqh[mi][3], smb + QH_OFF + off);
                LDSM_X4(aql[mi][0], aql[mi][1], aql[mi][2], aql[mi][3], smb + QL_OFF + off);
            }
            #pragma unroll
            for (int j = 0; j < 3; j++) {
                int row = 48 * nw + 16 * j + b_row;
                uint32_t off = (uint32_t)row * 256u
                             + (uint32_t)((2 * k + b_chnk) ^ (row & 7)) * 16u;
                LDSM_X4(bph[2*j][0], bph[2*j][1], bph[2*j+1][0], bph[2*j+1][1], smb + PH_OFF + off);
                LDSM_X4(bpl[2*j][0], bpl[2*j][1], bpl[2*j+1][0], bpl[2*j+1][1], smb + PL_OFF + off);
            }
            #pragma unroll
            for (int mi = 0; mi < 2; mi++)
                #pragma unroll
                for (int t = 0; t < 6; t++) {
                    MMA_BF16(cfr[mi][t], aqh[mi], bph[t]);
                    MMA_BF16(cfr[mi][t], aqh[mi], bpl[t]);
                    MMA_BF16(cfr[mi][t], aql[mi], bph[t]);
                }
        }

        // ---- epilogue: masked max over this half's columns
        #pragma unroll
        for (int mi = 0; mi < 2; mi++) {
            float r0 = -FLT_MAX, r1 = -FLT_MAX;
            #pragma unroll
            for (int t = 0; t < 6; t++) {
                int cb = 48 * nw + 8 * t + 2 * (lane & 3);
                float b0 = bias_s[cb], b1 = bias_s[cb + 1];
                r0 = fmaxf(r0, fmaxf(cfr[mi][t][0] + b0, cfr[mi][t][1] + b1));
                r1 = fmaxf(r1, fmaxf(cfr[mi][t][2] + b0, cfr[mi][t][3] + b1));
            }
            int row0 = 32 * mw + 16 * mi + (lane >> 2);
            atomicMax(&rowmax[row0],     enc_f(r0));
            atomicMax(&rowmax[row0 + 8], enc_f(r1));
        }
    }

    __syncthreads();
    if (tid < 3) {
        float s = 0.f;
        #pragma unroll
        for (int i = 0; i < 35; i++) s += dec_f(rowmax[tid * 35 + i]);
        out[(size_t)(bqg * 3 + tid) * (2 * BATCH) + z * BATCH + bp] = s;
    }
}

// ===================== launch =====================
extern "C" void kernel_launch(void* const* d_in, const int* in_sizes, int n_in,
                              void* d_out, int out_size)
{
    const float* qh   = (const float*)d_in[0];
    const float* ph   = (const float*)d_in[1];
    const float* nh   = (const float*)d_in[2];
    const float* W    = (const float*)d_in[3];
    const float* bias = (const float*)d_in[4];
    const void*  pm   = d_in[5];
    const void*  nm   = d_in[6];
    float* out = (float*)d_out;

    float *dq, *dpos, *dneg, *dpm, *dnm;
    cudaGetSymbolAddress((void**)&dq,   g_q);
    cudaGetSymbolAddress((void**)&dpos, g_pos);
    cudaGetSymbolAddress((void**)&dneg, g_neg);
    cudaGetSymbolAddress((void**)&dpm,  g_pmask);
    cudaGetSymbolAddress((void**)&dnm,  g_nmask);

    detect_mode_kernel<<<1, 256>>>((const unsigned int*)pm);
    expand_mask_kernel<<<(BATCH * LP + 255) / 256, 256>>>(pm, nm);

    proj_kernel<<<(BATCH * NQ + 63) / 64, 256>>>(qh, W, bias, dq, BATCH * NQ);
    proj_kernel<<<(BATCH * LP + 63) / 64, 256>>>(ph, W, bias, dpos, BATCH * LP);
    proj_kernel<<<(BATCH * LP + 63) / 64, 256>>>(nh, W, bias, dneg, BATCH * LP);

    norm_kernel<<<(BATCH * DIM + 255) / 256, 256>>>(dq, NQ);
    norm_kernel<<<(BATCH * DIM + 255) / 256, 256>>>(dpos, LP);
    norm_kernel<<<(BATCH * DIM + 255) / 256, 256>>>(dneg, LP);

    cudaFuncSetAttribute(maxsim_mma_kernel,
                         cudaFuncAttributeMaxDynamicSharedMemorySize, MS_SMEM);
    dim3 grid(BATCH, BATCH / 3, 2);
    maxsim_mma_kernel<<<grid, 256, MS_SMEM>>>(dq, dpos, dneg, dpm, dnm, out);
}

// round 9
// speedup vs baseline: 2.5229x; 1.3125x over previous
#include <cuda_runtime.h>
#include <cuda_bf16.h>
#include <math.h>
#include <float.h>
#include <stdint.h>

#define BATCH 96
#define NQ 35
#define LP 180
#define HID 768
#define DIM 128

// ===================== scratch (no allocation allowed) =====================
__device__ float g_q[BATCH * NQ * DIM];
__device__ float g_pos[BATCH * LP * DIM];
__device__ float g_neg[BATCH * LP * DIM];
__device__ float g_pmask[BATCH * LP];
__device__ float g_nmask[BATCH * LP];
__device__ int   g_mask_mode;

// pre-converted bf16 tiles in ldmatrix-swizzled layout
// q tiles: [hi/lo][32 groups][128 rows x 256B]
__device__ unsigned char g_qt[2][32][32768];
// p tiles: [hi/lo][side][bp][half][96 rows x 256B]
__device__ unsigned char g_pt[2][2][BATCH][2][24576];
// W^T tiles: [hi/lo][kc=6][128 rows x 256B]
__device__ unsigned char g_wt[2][6][32768];

// ===================== helpers =====================
__device__ __forceinline__ uint32_t smem_u32(const void* p) {
    uint32_t a;
    asm("{ .reg .u64 t; cvta.to.shared.u64 t, %1; cvt.u32.u64 %0, t; }" : "=r"(a) : "l"(p));
    return a;
}

#define LDSM_X4(r0, r1, r2, r3, addr) \
    asm volatile("ldmatrix.sync.aligned.m8n8.x4.shared.b16 {%0,%1,%2,%3}, [%4];" \
        : "=r"(r0), "=r"(r1), "=r"(r2), "=r"(r3) : "r"(addr))

#define MMA_BF16(c, a, b) \
    asm volatile("mma.sync.aligned.m16n8k16.row.col.f32.bf16.bf16.f32 " \
        "{%0,%1,%2,%3}, {%4,%5,%6,%7}, {%8,%9}, {%0,%1,%2,%3};" \
        : "+f"((c)[0]), "+f"((c)[1]), "+f"((c)[2]), "+f"((c)[3]) \
        : "r"((a)[0]), "r"((a)[1]), "r"((a)[2]), "r"((a)[3]), \
          "r"((b)[0]), "r"((b)[1]))

__device__ __forceinline__ uint32_t pack_bf16(float f0, float f1) {
    uint16_t u0 = __bfloat16_as_ushort(__float2bfloat16(f0));
    uint16_t u1 = __bfloat16_as_ushort(__float2bfloat16(f1));
    return (uint32_t)u0 | ((uint32_t)u1 << 16);
}
__device__ __forceinline__ float bf16_res(float f) {
    return f - __bfloat162float(__float2bfloat16(f));
}
__device__ __forceinline__ void pack8(const float4& v0, const float4& v1,
                                      uint4& hv, uint4& lv) {
    hv.x = pack_bf16(v0.x, v0.y); hv.y = pack_bf16(v0.z, v0.w);
    hv.z = pack_bf16(v1.x, v1.y); hv.w = pack_bf16(v1.z, v1.w);
    lv.x = pack_bf16(bf16_res(v0.x), bf16_res(v0.y));
    lv.y = pack_bf16(bf16_res(v0.z), bf16_res(v0.w));
    lv.z = pack_bf16(bf16_res(v1.x), bf16_res(v1.y));
    lv.w = pack_bf16(bf16_res(v1.z), bf16_res(v1.w));
}
__device__ __forceinline__ unsigned enc_f(float x) {
    unsigned u = __float_as_uint(x);
    return (u & 0x80000000u) ? ~u : (u | 0x80000000u);
}
__device__ __forceinline__ float dec_f(unsigned e) {
    return (e & 0x80000000u) ? __uint_as_float(e ^ 0x80000000u)
                             : __uint_as_float(~e);
}

// ===================== mask dtype detection =====================
__global__ void detect_mode_kernel(const unsigned int* __restrict__ m) {
    __shared__ int s_bf16, s_f32, s_gt1;
    if (threadIdx.x == 0) { s_bf16 = 0; s_f32 = 0; s_gt1 = 0; }
    __syncthreads();
    int lbf = 0, lf = 0, lg = 0;
    for (int i = threadIdx.x; i < (BATCH * LP) / 4; i += blockDim.x) {
        unsigned int w = m[i];
        if (w == 0x3F803F80u) lbf = 1;
        else if (w == 0x3F800000u) lf = 1;
        else if (w > 1u) lg = 1;
    }
    if (lbf) s_bf16 = 1;
    if (lf)  s_f32 = 1;
    if (lg)  s_gt1 = 1;
    __syncthreads();
    if (threadIdx.x == 0) {
        int mode;
        if (s_bf16)      mode = 3;
        else if (s_f32)  mode = 2;
        else if (s_gt1)  mode = 0;
        else             mode = 1;
        g_mask_mode = mode;
    }
}

__global__ void expand_mask_kernel(const void* __restrict__ pm, const void* __restrict__ nm) {
    int idx = blockIdx.x * blockDim.x + threadIdx.x;
    if (idx >= BATCH * LP) return;
    int mode = g_mask_mode;
    float pv, nv;
    if (mode == 0) {
        pv = ((const unsigned char*)pm)[idx] ? 1.f : 0.f;
        nv = ((const unsigned char*)nm)[idx] ? 1.f : 0.f;
    } else if (mode == 1) {
        pv = ((const int*)pm)[idx] ? 1.f : 0.f;
        nv = ((const int*)nm)[idx] ? 1.f : 0.f;
    } else if (mode == 2) {
        pv = (((const float*)pm)[idx] != 0.f) ? 1.f : 0.f;
        nv = (((const float*)nm)[idx] != 0.f) ? 1.f : 0.f;
    } else {
        pv = (__bfloat162float(((const __nv_bfloat16*)pm)[idx]) != 0.f) ? 1.f : 0.f;
        nv = (__bfloat162float(((const __nv_bfloat16*)nm)[idx]) != 0.f) ? 1.f : 0.f;
    }
    g_pmask[idx] = pv;
    g_nmask[idx] = nv;
}

// ===================== W^T -> bf16 hi/lo swizzled tiles =====================
// g_wt[.][kc] tile: row = d (0..127), k-chunk c (16B = 8 bf16 of h), swizzle c^(d&7)
__global__ void wt_convert_kernel(const float* __restrict__ W) {
    int idx = blockIdx.x * blockDim.x + threadIdx.x;   // 12288 = 6*128*16
    if (idx >= 6 * 128 * 16) return;
    int kc = idx >> 11;
    int rem = idx & 2047;
    int d = rem >> 4, c = rem & 15;
    int h0 = kc * 128 + c * 8;
    float w[8];
    #pragma unroll
    for (int e = 0; e < 8; e++) w[e] = W[(size_t)(h0 + e) * DIM + d];
    float4 v0 = make_float4(w[0], w[1], w[2], w[3]);
    float4 v1 = make_float4(w[4], w[5], w[6], w[7]);
    uint4 hv, lv; pack8(v0, v1, hv, lv);
    uint32_t off = (uint32_t)d * 256u + (uint32_t)(c ^ (d & 7)) * 16u;
    *(uint4*)&g_wt[0][kc][off] = hv;
    *(uint4*)&g_wt[1][kc][off] = lv;
}

// ===================== projection GEMM via mma.sync hi/lo =====================
// out[M,128] = A[M,768] @ W + b.  Block: 128 rows; B = g_wt tiles.
#define PJ_AH 0
#define PJ_AL 32768
#define PJ_BH 65536
#define PJ_BL 98304
#define PJ_SMEM 131072

__global__ __launch_bounds__(256) void proj_mma_kernel(
    const float* __restrict__ A, const float* __restrict__ bias,
    float* __restrict__ out, int M)
{
    extern __shared__ char sm[];
    uint32_t smb = smem_u32(sm);
    int tid = threadIdx.x;
    int lane = tid & 31;
    int wid = tid >> 5;
    int mw = wid >> 1;   // 0..3
    int nw = wid & 1;    // 0..1
    int row0 = blockIdx.x * 128;

    float cfr[2][8][4];
    #pragma unroll
    for (int mi = 0; mi < 2; mi++)
        #pragma unroll
        for (int t = 0; t < 8; t++)
            #pragma unroll
            for (int u = 0; u < 4; u++) cfr[mi][t][u] = 0.f;

    int a_row  = lane & 15;
    int a_chnk = lane >> 4;
    int b_row  = ((lane & 16) >> 1) + (lane & 7);
    int b_chnk = (lane >> 3) & 1;

    for (int kc = 0; kc < 6; kc++) {
        __syncthreads();
        // copy W^T tiles (already bf16 + swizzled)
        {
            const uint4* bh = (const uint4*)&g_wt[0][kc][0];
            const uint4* bl = (const uint4*)&g_wt[1][kc][0];
            for (int i = tid; i < 2048; i += 256) {
                *(uint4*)(sm + PJ_BH + i * 16) = bh[i];
                *(uint4*)(sm + PJ_BL + i * 16) = bl[i];
            }
        }
        // convert A chunk fp32 -> bf16 hi/lo swizzled
        for (int i = tid; i < 2048; i += 256) {
            int r = i >> 4, c = i & 15;
            int gr = row0 + r;
            float4 v0 = make_float4(0.f, 0.f, 0.f, 0.f), v1 = v0;
            if (gr < M) {
                const float* ar = A + (size_t)gr * HID + kc * 128 + c * 8;
                v0 = *(const float4*)ar;
                v1 = *(const float4*)(ar + 4);
            }
            uint4 hv, lv; pack8(v0, v1, hv, lv);
            uint32_t off = (uint32_t)r * 256u + (uint32_t)(c ^ (r & 7)) * 16u;
            *(uint4*)(sm + PJ_AH + off) = hv;
            *(uint4*)(sm + PJ_AL + off) = lv;
        }
        __syncthreads();

        #pragma unroll
        for (int k = 0; k < 8; k++) {
            uint32_t aqh[2][4], aql[2][4], bph[8][2], bpl[8][2];
            #pragma unroll
            for (int mi = 0; mi < 2; mi++) {
                int row = 32 * mw + 16 * mi + a_row;
                uint32_t off = (uint32_t)row * 256u
                             + (uint32_t)((2 * k + a_chnk) ^ (row & 7)) * 16u;
                LDSM_X4(aqh[mi][0], aqh[mi][1], aqh[mi][2], aqh[mi][3], smb + PJ_AH + off);
                LDSM_X4(aql[mi][0], aql[mi][1], aql[mi][2], aql[mi][3], smb + PJ_AL + off);
            }
            #pragma unroll
            for (int j = 0; j < 4; j++) {
                int row = 64 * nw + 16 * j + b_row;
                uint32_t off = (uint32_t)row * 256u
                             + (uint32_t)((2 * k + b_chnk) ^ (row & 7)) * 16u;
                LDSM_X4(bph[2*j][0], bph[2*j][1], bph[2*j+1][0], bph[2*j+1][1], smb + PJ_BH + off);
                LDSM_X4(bpl[2*j][0], bpl[2*j][1], bpl[2*j+1][0], bpl[2*j+1][1], smb + PJ_BL + off);
            }
            #pragma unroll
            for (int mi = 0; mi < 2; mi++)
                #pragma unroll
                for (int t = 0; t < 8; t++) {
                    MMA_BF16(cfr[mi][t], aqh[mi], bph[t]);
                    MMA_BF16(cfr[mi][t], aqh[mi], bpl[t]);
                    MMA_BF16(cfr[mi][t], aql[mi], bph[t]);
                }
        }
    }

    // epilogue: + bias, store fp32
    #pragma unroll
    for (int mi = 0; mi < 2; mi++) {
        int r0 = row0 + 32 * mw + 16 * mi + (lane >> 2);
        #pragma unroll
        for (int t = 0; t < 8; t++) {
            int col = 64 * nw + 8 * t + 2 * (lane & 3);
            float b0 = bias[col], b1 = bias[col + 1];
            if (r0 < M) {
                out[(size_t)r0 * DIM + col]     = cfr[mi][t][0] + b0;
                out[(size_t)r0 * DIM + col + 1] = cfr[mi][t][1] + b1;
            }
            if (r0 + 8 < M) {
                out[(size_t)(r0 + 8) * DIM + col]     = cfr[mi][t][2] + b0;
                out[(size_t)(r0 + 8) * DIM + col + 1] = cfr[mi][t][3] + b1;
            }
        }
    }
}

// ===================== sequence-axis normalization =====================
__global__ void norm_kernel(float* __restrict__ x, int L) {
    int idx = blockIdx.x * blockDim.x + threadIdx.x;
    if (idx >= BATCH * DIM) return;
    int b = idx >> 7;
    int d = idx & 127;
    float* base = x + (size_t)b * L * DIM + d;
    float s = 0.f;
    for (int l = 0; l < L; l++) { float v = base[(size_t)l * DIM]; s += v * v; }
    float inv = 1.f / fmaxf(sqrtf(s), 1e-12f);
    for (int l = 0; l < L; l++) base[(size_t)l * DIM] *= inv;
}

// ===================== tile converters (post-norm) =====================
// q: 32 groups of 105 rows padded to 128
__global__ void qt_convert_kernel() {
    int bqg = blockIdx.x;
    int tid = threadIdx.x;
    for (int i = tid; i < 128 * 16; i += 256) {
        int r = i >> 4, c = i & 15;
        float4 v0 = make_float4(0.f, 0.f, 0.f, 0.f), v1 = v0;
        if (r < 105) {
            const float* qrow = g_q + (size_t)(bqg * 105 + r) * DIM + c * 8;
            v0 = *(const float4*)qrow;
            v1 = *(const float4*)(qrow + 4);
        }
        uint4 hv, lv; pack8(v0, v1, hv, lv);
        uint32_t off = (uint32_t)r * 256u + (uint32_t)(c ^ (r & 7)) * 16u;
        *(uint4*)&g_qt[0][bqg][off] = hv;
        *(uint4*)&g_qt[1][bqg][off] = lv;
    }
}

// p: per (bp, half, side): 96 rows starting at l0 = half*84
__global__ void pt_convert_kernel() {
    int bp = blockIdx.x, h = blockIdx.y, z = blockIdx.z;
    const float* P = z ? g_neg : g_pos;
    int tid = threadIdx.x;
    int l0 = h * 84;
    for (int i = tid; i < 96 * 16; i += 256) {
        int r = i >> 4, c = i & 15;
        const float* prow = P + (size_t)(bp * LP + l0 + r) * DIM + c * 8;
        float4 v0 = *(const float4*)prow;
        float4 v1 = *(const float4*)(prow + 4);
        uint4 hv, lv; pack8(v0, v1, hv, lv);
        uint32_t off = (uint32_t)r * 256u + (uint32_t)(c ^ (r & 7)) * 16u;
        *(uint4*)&g_pt[0][z][bp][h][off] = hv;
        *(uint4*)&g_pt[1][z][bp][h][off] = lv;
    }
}

// ===================== mma.sync MaxSim (pre-converted tiles) =====================
#define QH_OFF 0
#define QL_OFF 32768
#define PH_OFF 65536
#define PL_OFF 90112
#define MS_SMEM (90112 + 24576)     // 112 KB dynamic

__global__ __launch_bounds__(256) void maxsim_mma_kernel(
    const float* __restrict__ Mpos, const float* __restrict__ Mneg,
    float* __restrict__ out)
{
    extern __shared__ char sm[];
    uint32_t smb = smem_u32(sm);
    __shared__ float    bias_s[96];
    __shared__ unsigned rowmax[128];

    int bp = blockIdx.x, bqg = blockIdx.y, z = blockIdx.z;
    const float* Mf = z ? Mneg : Mpos;
    int tid  = threadIdx.x;
    int lane = tid & 31;
    int wid  = tid >> 5;
    int mw = wid >> 1;
    int nw = wid & 1;

    if (tid < 128) rowmax[tid] = 0u;

    // ---- copy pre-converted q tiles (raw 32KB each)
    {
        const uint4* qh = (const uint4*)&g_qt[0][bqg][0];
        const uint4* ql = (const uint4*)&g_qt[1][bqg][0];
        for (int i = tid; i < 2048; i += 256) {
            *(uint4*)(sm + QH_OFF + i * 16) = qh[i];
            *(uint4*)(sm + QL_OFF + i * 16) = ql[i];
        }
    }

    int a_row  = lane & 15;
    int a_chnk = lane >> 4;
    int b_row  = ((lane & 16) >> 1) + (lane & 7);
    int b_chnk = (lane >> 3) & 1;

    #pragma unroll
    for (int h = 0; h < 2; h++) {
        int l0 = h * 84;
        __syncthreads();

        // ---- copy pre-converted p tiles (raw 24KB each)
        {
            const uint4* ph = (const uint4*)&g_pt[0][z][bp][h][0];
            const uint4* pl = (const uint4*)&g_pt[1][z][bp][h][0];
            for (int i = tid; i < 1536; i += 256) {
                *(uint4*)(sm + PH_OFF + i * 16) = ph[i];
                *(uint4*)(sm + PL_OFF + i * 16) = pl[i];
            }
        }
        if (tid < 96)
            bias_s[tid] = (Mf[bp * LP + l0 + tid] != 0.f) ? 0.f : -1e6f;
        __syncthreads();

        float cfr[2][6][4];
        #pragma unroll
        for (int mi = 0; mi < 2; mi++)
            #pragma unroll
            for (int t = 0; t < 6; t++)
                #pragma unroll
                for (int u = 0; u < 4; u++) cfr[mi][t][u] = 0.f;

        #pragma unroll
        for (int k = 0; k < 8; k++) {
            uint32_t aqh[2][4], aql[2][4], bph[6][2], bpl[6][2];
            #pragma unroll
            for (int mi = 0; mi < 2; mi++) {
                int row = 32 * mw + 16 * mi + a_row;
                uint32_t off = (uint32_t)row * 256u
                             + (uint32_t)((2 * k + a_chnk) ^ (row & 7)) * 16u;
                LDSM_X4(aqh[mi][0], aqh[mi][1], aqh[mi][2], aqh[mi][3], smb + QH_OFF + off);
                LDSM_X4(aql[mi][0], aql[mi][1], aql[mi][2], aql[mi][3], smb + QL_OFF + off);
            }
            #pragma unroll
            for (int j = 0; j < 3; j++) {
                int row = 48 * nw + 16 * j + b_row;
                uint32_t off = (uint32_t)row * 256u
                             + (uint32_t)((2 * k + b_chnk) ^ (row & 7)) * 16u;
                LDSM_X4(bph[2*j][0], bph[2*j][1], bph[2*j+1][0], bph[2*j+1][1], smb + PH_OFF + off);
                LDSM_X4(bpl[2*j][0], bpl[2*j][1], bpl[2*j+1][0], bpl[2*j+1][1], smb + PL_OFF + off);
            }
            #pragma unroll
            for (int mi = 0; mi < 2; mi++)
                #pragma unroll
                for (int t = 0; t < 6; t++) {
                    MMA_BF16(cfr[mi][t], aqh[mi], bph[t]);
                    MMA_BF16(cfr[mi][t], aqh[mi], bpl[t]);
                    MMA_BF16(cfr[mi][t], aql[mi], bph[t]);
                }
        }

        #pragma unroll
        for (int mi = 0; mi < 2; mi++) {
            float r0 = -FLT_MAX, r1 = -FLT_MAX;
            #pragma unroll
            for (int t = 0; t < 6; t++) {
                int cb = 48 * nw + 8 * t + 2 * (lane & 3);
                float b0 = bias_s[cb], b1 = bias_s[cb + 1];
                r0 = fmaxf(r0, fmaxf(cfr[mi][t][0] + b0, cfr[mi][t][1] + b1));
                r1 = fmaxf(r1, fmaxf(cfr[mi][t][2] + b0, cfr[mi][t][3] + b1));
            }
            int row0 = 32 * mw + 16 * mi + (lane >> 2);
            atomicMax(&rowmax[row0],     enc_f(r0));
            atomicMax(&rowmax[row0 + 8], enc_f(r1));
        }
    }

    __syncthreads();
    if (tid < 3) {
        float s = 0.f;
        #pragma unroll
        for (int i = 0; i < 35; i++) s += dec_f(rowmax[tid * 35 + i]);
        out[(size_t)(bqg * 3 + tid) * (2 * BATCH) + z * BATCH + bp] = s;
    }
}

// ===================== launch =====================
extern "C" void kernel_launch(void* const* d_in, const int* in_sizes, int n_in,
                              void* d_out, int out_size)
{
    const float* qh   = (const float*)d_in[0];
    const float* ph   = (const float*)d_in[1];
    const float* nh   = (const float*)d_in[2];
    const float* W    = (const float*)d_in[3];
    const float* bias = (const float*)d_in[4];
    const void*  pm   = d_in[5];
    const void*  nm   = d_in[6];
    float* out = (float*)d_out;

    float *dq, *dpos, *dneg, *dpm, *dnm;
    cudaGetSymbolAddress((void**)&dq,   g_q);
    cudaGetSymbolAddress((void**)&dpos, g_pos);
    cudaGetSymbolAddress((void**)&dneg, g_neg);
    cudaGetSymbolAddress((void**)&dpm,  g_pmask);
    cudaGetSymbolAddress((void**)&dnm,  g_nmask);

    detect_mode_kernel<<<1, 256>>>((const unsigned int*)pm);
    expand_mask_kernel<<<(BATCH * LP + 255) / 256, 256>>>(pm, nm);

    wt_convert_kernel<<<48, 256>>>(W);

    cudaFuncSetAttribute(proj_mma_kernel,
                         cudaFuncAttributeMaxDynamicSharedMemorySize, PJ_SMEM);
    proj_mma_kernel<<<(BATCH * NQ + 127) / 128, 256, PJ_SMEM>>>(qh, bias, dq, BATCH * NQ);
    proj_mma_kernel<<<(BATCH * LP + 127) / 128, 256, PJ_SMEM>>>(ph, bias, dpos, BATCH * LP);
    proj_mma_kernel<<<(BATCH * LP + 127) / 128, 256, PJ_SMEM>>>(nh, bias, dneg, BATCH * LP);

    norm_kernel<<<(BATCH * DIM + 255) / 256, 256>>>(dq, NQ);
    norm_kernel<<<(BATCH * DIM + 255) / 256, 256>>>(dpos, LP);
    norm_kernel<<<(BATCH * DIM + 255) / 256, 256>>>(dneg, LP);

    qt_convert_kernel<<<32, 256>>>();
    {
        dim3 pg(BATCH, 2, 2);
        pt_convert_kernel<<<pg, 256>>>();
    }

    cudaFuncSetAttribute(maxsim_mma_kernel,
                         cudaFuncAttributeMaxDynamicSharedMemorySize, MS_SMEM);
    dim3 grid(BATCH, BATCH / 3, 2);
    maxsim_mma_kernel<<<grid, 256, MS_SMEM>>>(dpm, dnm, out);
}

// round 11
// speedup vs baseline: 3.2389x; 1.2838x over previous
#include <cuda_runtime.h>
#include <cuda_bf16.h>
#include <math.h>
#include <float.h>
#include <stdint.h>

#define BATCH 96
#define NQ 35
#define LP 180
#define HID 768
#define DIM 128

#define QTILES 27            // ceil(3360/128)
#define MQ (BATCH * NQ)      // 3360
#define MP (BATCH * LP)      // 17280

// ===================== scratch (no allocation allowed) =====================
__device__ float g_q[MQ * DIM];
__device__ float g_pos[MP * DIM];
__device__ float g_neg[MP * DIM];
__device__ float g_pmask[BATCH * LP];
__device__ float g_nmask[BATCH * LP];
__device__ int   g_mask_mode;
__device__ float g_qinv[BATCH * DIM];
__device__ float g_pinv[2][BATCH * DIM];
__device__ float g_part[QTILES][2][BATCH][5];

// pre-converted bf16 tiles, ldmatrix-swizzled
__device__ unsigned char g_qt[2][QTILES][32768];          // flat q rows
__device__ unsigned char g_pt[2][2][BATCH][2][24576];     // [hi/lo][side][bp][half]
__device__ unsigned char g_wt[2][6][32768];               // W^T per k-chunk

// ===================== helpers =====================
__device__ __forceinline__ uint32_t smem_u32(const void* p) {
    uint32_t a;
    asm("{ .reg .u64 t; cvta.to.shared.u64 t, %1; cvt.u32.u64 %0, t; }" : "=r"(a) : "l"(p));
    return a;
}

#define LDSM_X4(r0, r1, r2, r3, addr) \
    asm volatile("ldmatrix.sync.aligned.m8n8.x4.shared.b16 {%0,%1,%2,%3}, [%4];" \
        : "=r"(r0), "=r"(r1), "=r"(r2), "=r"(r3) : "r"(addr))

#define MMA_BF16(c, a, b) \
    asm volatile("mma.sync.aligned.m16n8k16.row.col.f32.bf16.bf16.f32 " \
        "{%0,%1,%2,%3}, {%4,%5,%6,%7}, {%8,%9}, {%0,%1,%2,%3};" \
        : "+f"((c)[0]), "+f"((c)[1]), "+f"((c)[2]), "+f"((c)[3]) \
        : "r"((a)[0]), "r"((a)[1]), "r"((a)[2]), "r"((a)[3]), \
          "r"((b)[0]), "r"((b)[1]))

__device__ __forceinline__ uint32_t pack_bf16(float f0, float f1) {
    uint16_t u0 = __bfloat16_as_ushort(__float2bfloat16(f0));
    uint16_t u1 = __bfloat16_as_ushort(__float2bfloat16(f1));
    return (uint32_t)u0 | ((uint32_t)u1 << 16);
}
__device__ __forceinline__ float bf16_res(float f) {
    return f - __bfloat162float(__float2bfloat16(f));
}
__device__ __forceinline__ void pack8(const float4& v0, const float4& v1,
                                      uint4& hv, uint4& lv) {
    hv.x = pack_bf16(v0.x, v0.y); hv.y = pack_bf16(v0.z, v0.w);
    hv.z = pack_bf16(v1.x, v1.y); hv.w = pack_bf16(v1.z, v1.w);
    lv.x = pack_bf16(bf16_res(v0.x), bf16_res(v0.y));
    lv.y = pack_bf16(bf16_res(v0.z), bf16_res(v0.w));
    lv.z = pack_bf16(bf16_res(v1.x), bf16_res(v1.y));
    lv.w = pack_bf16(bf16_res(v1.z), bf16_res(v1.w));
}
__device__ __forceinline__ unsigned enc_f(float x) {
    unsigned u = __float_as_uint(x);
    return (u & 0x80000000u) ? ~u : (u | 0x80000000u);
}
__device__ __forceinline__ float dec_f(unsigned e) {
    return (e & 0x80000000u) ? __uint_as_float(e ^ 0x80000000u)
                             : __uint_as_float(~e);
}

// ===================== mask dtype detection =====================
__global__ void detect_mode_kernel(const unsigned int* __restrict__ m) {
    __shared__ int s_bf16, s_f32, s_gt1;
    if (threadIdx.x == 0) { s_bf16 = 0; s_f32 = 0; s_gt1 = 0; }
    __syncthreads();
    int lbf = 0, lf = 0, lg = 0;
    for (int i = threadIdx.x; i < (BATCH * LP) / 4; i += blockDim.x) {
        unsigned int w = m[i];
        if (w == 0x3F803F80u) lbf = 1;
        else if (w == 0x3F800000u) lf = 1;
        else if (w > 1u) lg = 1;
    }
    if (lbf) s_bf16 = 1;
    if (lf)  s_f32 = 1;
    if (lg)  s_gt1 = 1;
    __syncthreads();
    if (threadIdx.x == 0) {
        int mode;
        if (s_bf16)      mode = 3;
        else if (s_f32)  mode = 2;
        else if (s_gt1)  mode = 0;
        else             mode = 1;
        g_mask_mode = mode;
    }
}

__global__ void expand_mask_kernel(const void* __restrict__ pm, const void* __restrict__ nm) {
    int idx = blockIdx.x * blockDim.x + threadIdx.x;
    if (idx >= BATCH * LP) return;
    int mode = g_mask_mode;
    float pv, nv;
    if (mode == 0) {
        pv = ((const unsigned char*)pm)[idx] ? 1.f : 0.f;
        nv = ((const unsigned char*)nm)[idx] ? 1.f : 0.f;
    } else if (mode == 1) {
        pv = ((const int*)pm)[idx] ? 1.f : 0.f;
        nv = ((const int*)nm)[idx] ? 1.f : 0.f;
    } else if (mode == 2) {
        pv = (((const float*)pm)[idx] != 0.f) ? 1.f : 0.f;
        nv = (((const float*)nm)[idx] != 0.f) ? 1.f : 0.f;
    } else {
        pv = (__bfloat162float(((const __nv_bfloat16*)pm)[idx]) != 0.f) ? 1.f : 0.f;
        nv = (__bfloat162float(((const __nv_bfloat16*)nm)[idx]) != 0.f) ? 1.f : 0.f;
    }
    g_pmask[idx] = pv;
    g_nmask[idx] = nv;
}

// ===================== W^T -> bf16 hi/lo swizzled tiles =====================
__global__ void wt_convert_kernel(const float* __restrict__ W) {
    int idx = blockIdx.x * blockDim.x + threadIdx.x;
    if (idx >= 6 * 128 * 16) return;
    int kc = idx >> 11;
    int rem = idx & 2047;
    int d = rem >> 4, c = rem & 15;
    int h0 = kc * 128 + c * 8;
    float w[8];
    #pragma unroll
    for (int e = 0; e < 8; e++) w[e] = W[(size_t)(h0 + e) * DIM + d];
    float4 v0 = make_float4(w[0], w[1], w[2], w[3]);
    float4 v1 = make_float4(w[4], w[5], w[6], w[7]);
    uint4 hv, lv; pack8(v0, v1, hv, lv);
    uint32_t off = (uint32_t)d * 256u + (uint32_t)(c ^ (d & 7)) * 16u;
    *(uint4*)&g_wt[0][kc][off] = hv;
    *(uint4*)&g_wt[1][kc][off] = lv;
}

// ===================== merged projection GEMM (all three inputs, one launch) ====
#define PJ_AH 0
#define PJ_AL 32768
#define PJ_BH 65536
#define PJ_BL 98304
#define PJ_SMEM 131072

__global__ __launch_bounds__(256) void proj_mma_kernel(
    const float* __restrict__ Aq, const float* __restrict__ Ap,
    const float* __restrict__ An, const float* __restrict__ bias)
{
    extern __shared__ char sm[];
    uint32_t smb = smem_u32(sm);
    int tid = threadIdx.x;
    int lane = tid & 31;
    int wid = tid >> 5;
    int mw = wid >> 1;
    int nw = wid & 1;

    int bx = blockIdx.x;
    const float* A; float* out; int row0, M;
    if (bx < QTILES)        { A = Aq; out = g_q;   row0 = bx * 128;            M = MQ; }
    else if (bx < QTILES+135){ A = Ap; out = g_pos; row0 = (bx-QTILES) * 128;   M = MP; }
    else                    { A = An; out = g_neg; row0 = (bx-QTILES-135)*128; M = MP; }

    float cfr[2][8][4];
    #pragma unroll
    for (int mi = 0; mi < 2; mi++)
        #pragma unroll
        for (int t = 0; t < 8; t++)
            #pragma unroll
            for (int u = 0; u < 4; u++) cfr[mi][t][u] = 0.f;

    int a_row  = lane & 15;
    int a_chnk = lane >> 4;
    int b_row  = ((lane & 16) >> 1) + (lane & 7);
    int b_chnk = (lane >> 3) & 1;

    for (int kc = 0; kc < 6; kc++) {
        __syncthreads();
        {
            const uint4* bh = (const uint4*)&g_wt[0][kc][0];
            const uint4* bl = (const uint4*)&g_wt[1][kc][0];
            for (int i = tid; i < 2048; i += 256) {
                *(uint4*)(sm + PJ_BH + i * 16) = bh[i];
                *(uint4*)(sm + PJ_BL + i * 16) = bl[i];
            }
        }
        for (int i = tid; i < 2048; i += 256) {
            int r = i >> 4, c = i & 15;
            int gr = row0 + r;
            float4 v0 = make_float4(0.f, 0.f, 0.f, 0.f), v1 = v0;
            if (gr < M) {
                const float* ar = A + (size_t)gr * HID + kc * 128 + c * 8;
                v0 = *(const float4*)ar;
                v1 = *(const float4*)(ar + 4);
            }
            uint4 hv, lv; pack8(v0, v1, hv, lv);
            uint32_t off = (uint32_t)r * 256u + (uint32_t)(c ^ (r & 7)) * 16u;
            *(uint4*)(sm + PJ_AH + off) = hv;
            *(uint4*)(sm + PJ_AL + off) = lv;
        }
        __syncthreads();

        #pragma unroll
        for (int k = 0; k < 8; k++) {
            uint32_t aqh[2][4], aql[2][4], bph[8][2], bpl[8][2];
            #pragma unroll
            for (int mi = 0; mi < 2; mi++) {
                int row = 32 * mw + 16 * mi + a_row;
                uint32_t off = (uint32_t)row * 256u
                             + (uint32_t)((2 * k + a_chnk) ^ (row & 7)) * 16u;
                LDSM_X4(aqh[mi][0], aqh[mi][1], aqh[mi][2], aqh[mi][3], smb + PJ_AH + off);
                LDSM_X4(aql[mi][0], aql[mi][1], aql[mi][2], aql[mi][3], smb + PJ_AL + off);
            }
            #pragma unroll
            for (int j = 0; j < 4; j++) {
                int row = 64 * nw + 16 * j + b_row;
                uint32_t off = (uint32_t)row * 256u
                             + (uint32_t)((2 * k + b_chnk) ^ (row & 7)) * 16u;
                LDSM_X4(bph[2*j][0], bph[2*j][1], bph[2*j+1][0], bph[2*j+1][1], smb + PJ_BH + off);
                LDSM_X4(bpl[2*j][0], bpl[2*j][1], bpl[2*j+1][0], bpl[2*j+1][1], smb + PJ_BL + off);
            }
            #pragma unroll
            for (int mi = 0; mi < 2; mi++)
                #pragma unroll
                for (int t = 0; t < 8; t++) {
                    MMA_BF16(cfr[mi][t], aqh[mi], bph[t]);
                    MMA_BF16(cfr[mi][t], aqh[mi], bpl[t]);
                    MMA_BF16(cfr[mi][t], aql[mi], bph[t]);
                }
        }
    }

    #pragma unroll
    for (int mi = 0; mi < 2; mi++) {
        int r0 = row0 + 32 * mw + 16 * mi + (lane >> 2);
        #pragma unroll
        for (int t = 0; t < 8; t++) {
            int col = 64 * nw + 8 * t + 2 * (lane & 3);
            float b0 = bias[col], b1 = bias[col + 1];
            if (r0 < M) {
                out[(size_t)r0 * DIM + col]     = cfr[mi][t][0] + b0;
                out[(size_t)r0 * DIM + col + 1] = cfr[mi][t][1] + b1;
            }
            if (r0 + 8 < M) {
                out[(size_t)(r0 + 8) * DIM + col]     = cfr[mi][t][2] + b0;
                out[(size_t)(r0 + 8) * DIM + col + 1] = cfr[mi][t][3] + b1;
            }
        }
    }
}

// ===================== norm factors (no in-place pass) =====================
// blockIdx.y: 0 = q (L=35), 1 = pos, 2 = neg (L=180)
__global__ void norm_factor_kernel() {
    int idx = blockIdx.x * blockDim.x + threadIdx.x;
    if (idx >= BATCH * DIM) return;
    int which = blockIdx.y;
    const float* src = (which == 0) ? g_q : (which == 1) ? g_pos : g_neg;
    int L = (which == 0) ? NQ : LP;
    int b = idx >> 7, d = idx & 127;
    const float* base = src + (size_t)b * L * DIM + d;
    float s = 0.f;
    for (int l = 0; l < L; l++) { float v = base[(size_t)l * DIM]; s += v * v; }
    float inv = 1.f / fmaxf(sqrtf(s), 1e-12f);
    if (which == 0) g_qinv[idx] = inv;
    else            g_pinv[which - 1][idx] = inv;
}

// ===================== tile converters (apply norm inline) =====================
__global__ void qt_convert_kernel() {
    int t = blockIdx.x;
    int tid = threadIdx.x;
    for (int i = tid; i < 128 * 16; i += 256) {
        int r = i >> 4, c = i & 15;
        int gr = t * 128 + r;
        float4 v0 = make_float4(0.f, 0.f, 0.f, 0.f), v1 = v0;
        if (gr < MQ) {
            int b = gr / 35;
            const float* qrow = g_q + (size_t)gr * DIM + c * 8;
            const float* iv = g_qinv + b * DIM + c * 8;
            float4 r0 = *(const float4*)qrow;
            float4 r1 = *(const float4*)(qrow + 4);
            float4 i0 = *(const float4*)iv;
            float4 i1 = *(const float4*)(iv + 4);
            v0 = make_float4(r0.x * i0.x, r0.y * i0.y, r0.z * i0.z, r0.w * i0.w);
            v1 = make_float4(r1.x * i1.x, r1.y * i1.y, r1.z * i1.z, r1.w * i1.w);
        }
        uint4 hv, lv; pack8(v0, v1, hv, lv);
        uint32_t off = (uint32_t)r * 256u + (uint32_t)(c ^ (r & 7)) * 16u;
        *(uint4*)&g_qt[0][t][off] = hv;
        *(uint4*)&g_qt[1][t][off] = lv;
    }
}

__global__ void pt_convert_kernel() {
    int bp = blockIdx.x, h = blockIdx.y, z = blockIdx.z;
    const float* P = z ? g_neg : g_pos;
    const float* inv = g_pinv[z] + bp * DIM;
    int tid = threadIdx.x;
    int l0 = h * 84;
    for (int i = tid; i < 96 * 16; i += 256) {
        int r = i >> 4, c = i & 15;
        const float* prow = P + (size_t)(bp * LP + l0 + r) * DIM + c * 8;
        float4 r0 = *(const float4*)prow;
        float4 r1 = *(const float4*)(prow + 4);
        float4 i0 = *(const float4*)(inv + c * 8);
        float4 i1 = *(const float4*)(inv + c * 8 + 4);
        float4 v0 = make_float4(r0.x * i0.x, r0.y * i0.y, r0.z * i0.z, r0.w * i0.w);
        float4 v1 = make_float4(r1.x * i1.x, r1.y * i1.y, r1.z * i1.z, r1.w * i1.w);
        uint4 hv, lv; pack8(v0, v1, hv, lv);
        uint32_t off = (uint32_t)r * 256u + (uint32_t)(c ^ (r & 7)) * 16u;
        *(uint4*)&g_pt[0][z][bp][h][off] = hv;
        *(uint4*)&g_pt[1][z][bp][h][off] = lv;
    }
}

// ===================== mma.sync MaxSim (flat q tiles) =====================
#define QH_OFF 0
#define QL_OFF 32768
#define PH_OFF 65536
#define PL_OFF 90112
#define MS_SMEM (90112 + 24576)     // 112 KB dynamic

__global__ __launch_bounds__(256) void maxsim_mma_kernel(
    const float* __restrict__ Mpos, const float* __restrict__ Mneg)
{
    extern __shared__ char sm[];
    uint32_t smb = smem_u32(sm);
    __shared__ float    bias_s[96];
    __shared__ unsigned rowmax[128];

    int bp = blockIdx.x, qt = blockIdx.y, z = blockIdx.z;
    const float* Mf = z ? Mneg : Mpos;
    int tid  = threadIdx.x;
    int lane = tid & 31;
    int wid  = tid >> 5;
    int mw = wid >> 1;
    int nw = wid & 1;

    if (tid < 128) rowmax[tid] = 0u;

    {
        const uint4* qh = (const uint4*)&g_qt[0][qt][0];
        const uint4* ql = (const uint4*)&g_qt[1][qt][0];
        for (int i = tid; i < 2048; i += 256) {
            *(uint4*)(sm + QH_OFF + i * 16) = qh[i];
            *(uint4*)(sm + QL_OFF + i * 16) = ql[i];
        }
    }

    int a_row  = lane & 15;
    int a_chnk = lane >> 4;
    int b_row  = ((lane & 16) >> 1) + (lane & 7);
    int b_chnk = (lane >> 3) & 1;

    #pragma unroll
    for (int h = 0; h < 2; h++) {
        int l0 = h * 84;
        __syncthreads();

        {
            const uint4* ph = (const uint4*)&g_pt[0][z][bp][h][0];
            const uint4* pl = (const uint4*)&g_pt[1][z][bp][h][0];
            for (int i = tid; i < 1536; i += 256) {
                *(uint4*)(sm + PH_OFF + i * 16) = ph[i];
                *(uint4*)(sm + PL_OFF + i * 16) = pl[i];
            }
        }
        if (tid < 96)
            bias_s[tid] = (Mf[bp * LP + l0 + tid] != 0.f) ? 0.f : -1e6f;
        __syncthreads();

        float cfr[2][6][4];
        #pragma unroll
        for (int mi = 0; mi < 2; mi++)
            #pragma unroll
            for (int t = 0; t < 6; t++)
                #pragma unroll
                for (int u = 0; u < 4; u++) cfr[mi][t][u] = 0.f;

        #pragma unroll
        for (int k = 0; k < 8; k++) {
            uint32_t aqh[2][4], aql[2][4], bph[6][2], bpl[6][2];
            #pragma unroll
            for (int mi = 0; mi < 2; mi++) {
                int row = 32 * mw + 16 * mi + a_row;
                uint32_t off = (uint32_t)row * 256u
                             + (uint32_t)((2 * k + a_chnk) ^ (row & 7)) * 16u;
                LDSM_X4(aqh[mi][0], aqh[mi][1], aqh[mi][2], aqh[mi][3], smb + QH_OFF + off);
                LDSM_X4(aql[mi][0], aql[mi][1], aql[mi][2], aql[mi][3], smb + QL_OFF + off);
            }
            #pragma unroll
            for (int j = 0; j < 3; j++) {
                int row = 48 * nw + 16 * j + b_row;
                uint32_t off = (uint32_t)row * 256u
                             + (uint32_t)((2 * k + b_chnk) ^ (row & 7)) * 16u;
                LDSM_X4(bph[2*j][0], bph[2*j][1], bph[2*j+1][0], bph[2*j+1][1], smb + PH_OFF + off);
                LDSM_X4(bpl[2*j][0], bpl[2*j][1], bpl[2*j+1][0], bpl[2*j+1][1], smb + PL_OFF + off);
            }
            #pragma unroll
            for (int mi = 0; mi < 2; mi++)
                #pragma unroll
                for (int t = 0; t < 6; t++) {
                    MMA_BF16(cfr[mi][t], aqh[mi], bph[t]);
                    MMA_BF16(cfr[mi][t], aqh[mi], bpl[t]);
                    MMA_BF16(cfr[mi][t], aql[mi], bph[t]);
                }
        }

        #pragma unroll
        for (int mi = 0; mi < 2; mi++) {
            float r0 = -FLT_MAX, r1 = -FLT_MAX;
            #pragma unroll
            for (int t = 0; t < 6; t++) {
                int cb = 48 * nw + 8 * t + 2 * (lane & 3);
                float b0 = bias_s[cb], b1 = bias_s[cb + 1];
                r0 = fmaxf(r0, fmaxf(cfr[mi][t][0] + b0, cfr[mi][t][1] + b1));
                r1 = fmaxf(r1, fmaxf(cfr[mi][t][2] + b0, cfr[mi][t][3] + b1));
            }
            int row0 = 32 * mw + 16 * mi + (lane >> 2);
            atomicMax(&rowmax[row0],     enc_f(r0));
            atomicMax(&rowmax[row0 + 8], enc_f(r1));
        }
    }

    __syncthreads();
    // segmented per-bq partial sums (deterministic, warp-parallel)
    if (wid < 5) {
        int gr0 = qt * 128;
        int bq  = gr0 / 35 + wid;
        int start = max(bq * 35, gr0);
        int end   = min(bq * 35 + 35, min(gr0 + 128, MQ));
        float s = 0.f;
        for (int r = start + lane; r < end; r += 32)
            s += dec_f(rowmax[r - gr0]);
        #pragma unroll
        for (int o = 16; o > 0; o >>= 1)
            s += __shfl_xor_sync(0xffffffffu, s, o);
        if (lane == 0)
            g_part[qt][z][bp][wid] = (start < end) ? s : 0.f;
    }
}

// ===================== final per-bq assembly =====================
__global__ void final_sum_kernel(float* __restrict__ out) {
    int idx = blockIdx.x * blockDim.x + threadIdx.x;
    if (idx >= BATCH * 2 * BATCH) return;
    int bq = idx / (2 * BATCH);
    int rem = idx % (2 * BATCH);
    int z = rem / BATCH, bp = rem % BATCH;
    int t0 = (bq * 35) / 128;
    int t1 = (bq * 35 + 34) / 128;
    float s = 0.f;
    for (int t = t0; t <= t1; t++) {
        int seg = bq - (t * 128) / 35;
        if (seg >= 0 && seg < 5) s += g_part[t][z][bp][seg];
    }
    out[(size_t)bq * (2 * BATCH) + z * BATCH + bp] = s;
}

// ===================== launch =====================
extern "C" void kernel_launch(void* const* d_in, const int* in_sizes, int n_in,
                              void* d_out, int out_size)
{
    const float* qh   = (const float*)d_in[0];
    const float* ph   = (const float*)d_in[1];
    const float* nh   = (const float*)d_in[2];
    const float* W    = (const float*)d_in[3];
    const float* bias = (const float*)d_in[4];
    const void*  pm   = d_in[5];
    const void*  nm   = d_in[6];
    float* out = (float*)d_out;

    float *dpm, *dnm;
    cudaGetSymbolAddress((void**)&dpm, g_pmask);
    cudaGetSymbolAddress((void**)&dnm, g_nmask);

    detect_mode_kernel<<<1, 256>>>((const unsigned int*)pm);
    expand_mask_kernel<<<(BATCH * LP + 255) / 256, 256>>>(pm, nm);

    wt_convert_kernel<<<48, 256>>>(W);

    cudaFuncSetAttribute(proj_mma_kernel,
                         cudaFuncAttributeMaxDynamicSharedMemorySize, PJ_SMEM);
    proj_mma_kernel<<<QTILES + 2 * 135, 256, PJ_SMEM>>>(qh, ph, nh, bias);

    {
        dim3 ng((BATCH * DIM + 255) / 256, 3);
        norm_factor_kernel<<<ng, 256>>>();
    }

    qt_convert_kernel<<<QTILES, 256>>>();
    {
        dim3 pg(BATCH, 2, 2);
        pt_convert_kernel<<<pg, 256>>>();
    }

    cudaFuncSetAttribute(maxsim_mma_kernel,
                         cudaFuncAttributeMaxDynamicSharedMemorySize, MS_SMEM);
    dim3 grid(BATCH, QTILES, 2);
    maxsim_mma_kernel<<<grid, 256, MS_SMEM>>>(dpm, dnm);

    final_sum_kernel<<<(BATCH * 2 * BATCH + 255) / 256, 256>>>(out);
}